// round 1
// baseline (speedup 1.0000x reference)
#include <cuda_runtime.h>

#define B_ 8
#define S_ 1024
#define E_ 768
#define H_ 12
#define D_ 64
#define M_ (B_*S_)   // 8192

// Scratch (allocations are forbidden; use device globals)
__device__ float g_q[B_*H_*S_*D_];
__device__ float g_k[B_*H_*S_*D_];
__device__ float g_v[B_*H_*S_*D_];
__device__ float g_x[B_*S_*E_];   // attention output, already head-concatenated [B,S,E]

// ---------------------------------------------------------------------------
// Kernel 1: fused QKV projection.
// C[m, (h,d)] = sum_e hid[m,e] * W[h,e,d] + bias[h,d]
// grid = (M/64, 3*H). blockIdx.y selects (proj, head). 64x64 tile, K-tile 16,
// 256 threads, 4x4 microtile. Output scattered to [B,H,S,D] for attention.
// ---------------------------------------------------------------------------
__global__ __launch_bounds__(256)
void qkv_kernel(const float* __restrict__ hid,
                const float* __restrict__ Wq, const float* __restrict__ Wk,
                const float* __restrict__ Wv,
                const float* __restrict__ bq, const float* __restrict__ bk,
                const float* __restrict__ bv)
{
    __shared__ float AsT[16][64];   // [k][m]
    __shared__ float Bs [16][64];   // [k][n]

    const int tid = threadIdx.x;
    const int tx = tid & 15, ty = tid >> 4;
    const int m0 = blockIdx.x * 64;
    const int nb = blockIdx.y;
    const int proj = nb / H_;            // 0:q 1:k 2:v
    const int h = nb - proj * H_;

    const float* W    = (proj == 0) ? Wq : (proj == 1) ? Wk : Wv;
    const float* bias = (proj == 0) ? bq : (proj == 1) ? bk : bv;
    float* out        = (proj == 0) ? g_q : (proj == 1) ? g_k : g_v;
    const float* Wh = W + (size_t)h * E_ * D_;

    float acc[4][4] = {};

    const int a_row = tid >> 2;          // 0..63
    const int a_k   = (tid & 3) * 4;     // 0,4,8,12
    const int b_k   = tid >> 4;          // 0..15
    const int b_d   = (tid & 15) * 4;    // 0..60

    for (int k0 = 0; k0 < E_; k0 += 16) {
        float4 av = *(const float4*)&hid[(size_t)(m0 + a_row) * E_ + k0 + a_k];
        AsT[a_k + 0][a_row] = av.x;
        AsT[a_k + 1][a_row] = av.y;
        AsT[a_k + 2][a_row] = av.z;
        AsT[a_k + 3][a_row] = av.w;
        *(float4*)&Bs[b_k][b_d] =
            *(const float4*)&Wh[(size_t)(k0 + b_k) * D_ + b_d];
        __syncthreads();
#pragma unroll
        for (int kk = 0; kk < 16; kk++) {
            float4 a4 = *(const float4*)&AsT[kk][ty * 4];
            float4 b4 = *(const float4*)&Bs[kk][tx * 4];
            float a[4] = {a4.x, a4.y, a4.z, a4.w};
            float b[4] = {b4.x, b4.y, b4.z, b4.w};
#pragma unroll
            for (int i = 0; i < 4; i++)
#pragma unroll
                for (int j = 0; j < 4; j++)
                    acc[i][j] += a[i] * b[j];
        }
        __syncthreads();
    }

    float4 bb = *(const float4*)&bias[h * D_ + tx * 4];
#pragma unroll
    for (int i = 0; i < 4; i++) {
        int m = m0 + ty * 4 + i;
        int b = m >> 10;         // / S_
        int s = m & (S_ - 1);
        float* orow = out + (((size_t)(b * H_ + h)) * S_ + s) * D_;
        float4 ov = make_float4(acc[i][0] + bb.x, acc[i][1] + bb.y,
                                acc[i][2] + bb.z, acc[i][3] + bb.w);
        *(float4*)&orow[tx * 4] = ov;
    }
}

// ---------------------------------------------------------------------------
// Kernel 2: flash attention (fp32, non-causal).
// grid = (S/64, B*H), 256 threads. Each block: 64 Q rows, loop over 16 KV
// tiles of 64 rows. Smem operands are k-major for conflict-free LDS.128.
// Output written head-concatenated into g_x [B,S,E].
// ---------------------------------------------------------------------------
__global__ __launch_bounds__(256)
void attn_kernel()
{
    extern __shared__ float sm[];
    float* QsT = sm;               // [d][qrow]   64*64
    float* KsT = sm + 4096;        // [d][kvrow]  64*64
    float* Vs  = sm + 8192;        // [kvrow][d]  64*64
    float* Ps  = sm + 12288;       // [kvrow][qrow] 64*65 (pad for stores)

    const int tid = threadIdx.x;
    const int tx = tid & 15, ty = tid >> 4;
    const int bh = blockIdx.y;          // b*H + h
    const int s0 = blockIdx.x * 64;
    const int b = bh / H_;
    const int h = bh - b * H_;

    const float* Q = g_q + (size_t)bh * S_ * D_;
    const float* K = g_k + (size_t)bh * S_ * D_;
    const float* V = g_v + (size_t)bh * S_ * D_;

    // load Q tile, transposed to [d][qrow]
#pragma unroll
    for (int p = 0; p < 4; p++) {
        int fid = p * 256 + tid;
        int row = fid >> 4;
        int dq  = (fid & 15) * 4;
        float4 qv = *(const float4*)&Q[(size_t)(s0 + row) * D_ + dq];
        QsT[(dq + 0) * 64 + row] = qv.x;
        QsT[(dq + 1) * 64 + row] = qv.y;
        QsT[(dq + 2) * 64 + row] = qv.z;
        QsT[(dq + 3) * 64 + row] = qv.w;
    }

    float m_i[4], l_i[4], o[4][4];
#pragma unroll
    for (int i = 0; i < 4; i++) {
        m_i[i] = -1e30f; l_i[i] = 0.f;
#pragma unroll
        for (int j = 0; j < 4; j++) o[i][j] = 0.f;
    }

    for (int t0 = 0; t0 < S_; t0 += 64) {
        // load K (transposed) and V tiles
#pragma unroll
        for (int p = 0; p < 4; p++) {
            int fid = p * 256 + tid;
            int row = fid >> 4;
            int dq  = (fid & 15) * 4;
            float4 kv4 = *(const float4*)&K[(size_t)(t0 + row) * D_ + dq];
            KsT[(dq + 0) * 64 + row] = kv4.x;
            KsT[(dq + 1) * 64 + row] = kv4.y;
            KsT[(dq + 2) * 64 + row] = kv4.z;
            KsT[(dq + 3) * 64 + row] = kv4.w;
            *(float4*)&Vs[row * 64 + dq] =
                *(const float4*)&V[(size_t)(t0 + row) * D_ + dq];
        }
        __syncthreads();

        // S = Q K^T (per-thread 4x4)
        float sc[4][4] = {};
#pragma unroll
        for (int kd = 0; kd < 64; kd++) {
            float4 a4 = *(const float4*)&QsT[kd * 64 + ty * 4];
            float4 b4 = *(const float4*)&KsT[kd * 64 + tx * 4];
            float a[4] = {a4.x, a4.y, a4.z, a4.w};
            float bb[4] = {b4.x, b4.y, b4.z, b4.w};
#pragma unroll
            for (int i = 0; i < 4; i++)
#pragma unroll
                for (int j = 0; j < 4; j++)
                    sc[i][j] += a[i] * bb[j];
        }

        // online softmax (rows owned by (ty,i), 16 tx lanes share a row)
#pragma unroll
        for (int i = 0; i < 4; i++) {
            float mx = -1e30f;
#pragma unroll
            for (int j = 0; j < 4; j++) {
                sc[i][j] *= 0.125f;          // 1/sqrt(64)
                mx = fmaxf(mx, sc[i][j]);
            }
#pragma unroll
            for (int off = 8; off > 0; off >>= 1)
                mx = fmaxf(mx, __shfl_xor_sync(0xffffffffu, mx, off));
            float mnew = fmaxf(m_i[i], mx);
            float corr = __expf(m_i[i] - mnew);
            float rs = 0.f;
#pragma unroll
            for (int j = 0; j < 4; j++) {
                float p = __expf(sc[i][j] - mnew);
                Ps[(tx * 4 + j) * 65 + ty * 4 + i] = p;
                rs += p;
            }
#pragma unroll
            for (int off = 8; off > 0; off >>= 1)
                rs += __shfl_xor_sync(0xffffffffu, rs, off);
            l_i[i] = l_i[i] * corr + rs;
            m_i[i] = mnew;
#pragma unroll
            for (int j = 0; j < 4; j++) o[i][j] *= corr;
        }
        __syncthreads();

        // O += P @ V
#pragma unroll
        for (int kd = 0; kd < 64; kd++) {
            float pr[4];
#pragma unroll
            for (int i = 0; i < 4; i++)
                pr[i] = Ps[kd * 65 + ty * 4 + i];
            float4 v4 = *(const float4*)&Vs[kd * 64 + tx * 4];
            float vv[4] = {v4.x, v4.y, v4.z, v4.w};
#pragma unroll
            for (int i = 0; i < 4; i++)
#pragma unroll
                for (int j = 0; j < 4; j++)
                    o[i][j] += pr[i] * vv[j];
        }
        __syncthreads();
    }

    // finalize + write head-concatenated
#pragma unroll
    for (int i = 0; i < 4; i++) {
        float inv = 1.f / l_i[i];
        int qr = s0 + ty * 4 + i;
        float* row = g_x + ((size_t)b * S_ + qr) * E_ + h * D_;
        float4 ov = make_float4(o[i][0] * inv, o[i][1] * inv,
                                o[i][2] * inv, o[i][3] * inv);
        *(float4*)&row[tx * 4] = ov;
    }
}

// ---------------------------------------------------------------------------
// Kernel 3: output projection.  out = g_x @ Wo + bo.  grid = (M/64, E/64).
// ---------------------------------------------------------------------------
__global__ __launch_bounds__(256)
void proj_kernel(const float* __restrict__ Wo, const float* __restrict__ bo,
                 float* __restrict__ out)
{
    __shared__ float AsT[16][64];
    __shared__ float Bs [16][64];

    const int tid = threadIdx.x;
    const int tx = tid & 15, ty = tid >> 4;
    const int m0 = blockIdx.x * 64;
    const int n0 = blockIdx.y * 64;

    float acc[4][4] = {};

    const int a_row = tid >> 2;
    const int a_k   = (tid & 3) * 4;
    const int b_k   = tid >> 4;
    const int b_d   = (tid & 15) * 4;

    for (int k0 = 0; k0 < E_; k0 += 16) {
        float4 av = *(const float4*)&g_x[(size_t)(m0 + a_row) * E_ + k0 + a_k];
        AsT[a_k + 0][a_row] = av.x;
        AsT[a_k + 1][a_row] = av.y;
        AsT[a_k + 2][a_row] = av.z;
        AsT[a_k + 3][a_row] = av.w;
        *(float4*)&Bs[b_k][b_d] =
            *(const float4*)&Wo[(size_t)(k0 + b_k) * E_ + n0 + b_d];
        __syncthreads();
#pragma unroll
        for (int kk = 0; kk < 16; kk++) {
            float4 a4 = *(const float4*)&AsT[kk][ty * 4];
            float4 b4 = *(const float4*)&Bs[kk][tx * 4];
            float a[4] = {a4.x, a4.y, a4.z, a4.w};
            float b[4] = {b4.x, b4.y, b4.z, b4.w};
#pragma unroll
            for (int i = 0; i < 4; i++)
#pragma unroll
                for (int j = 0; j < 4; j++)
                    acc[i][j] += a[i] * b[j];
        }
        __syncthreads();
    }

    float4 bb = *(const float4*)&bo[n0 + tx * 4];
#pragma unroll
    for (int i = 0; i < 4; i++) {
        int m = m0 + ty * 4 + i;
        float4 ov = make_float4(acc[i][0] + bb.x, acc[i][1] + bb.y,
                                acc[i][2] + bb.z, acc[i][3] + bb.w);
        *(float4*)&out[(size_t)m * E_ + n0 + tx * 4] = ov;
    }
}

// ---------------------------------------------------------------------------

extern "C" void kernel_launch(void* const* d_in, const int* in_sizes, int n_in,
                              void* d_out, int out_size)
{
    const float* hid = (const float*)d_in[0];
    const float* Wq  = (const float*)d_in[1];
    const float* Wk  = (const float*)d_in[2];
    const float* Wv  = (const float*)d_in[3];
    const float* bq  = (const float*)d_in[4];
    const float* bk  = (const float*)d_in[5];
    const float* bv  = (const float*)d_in[6];
    const float* Wo  = (const float*)d_in[7];
    const float* bo  = (const float*)d_in[8];
    float* out = (float*)d_out;

    const int attn_smem = (3 * 64 * 64 + 64 * 65) * (int)sizeof(float); // 65792
    cudaFuncSetAttribute(attn_kernel,
                         cudaFuncAttributeMaxDynamicSharedMemorySize, attn_smem);

    qkv_kernel<<<dim3(M_ / 64, 3 * H_), 256>>>(hid, Wq, Wk, Wv, bq, bk, bv);
    attn_kernel<<<dim3(S_ / 64, B_ * H_), 256, attn_smem>>>();
    proj_kernel<<<dim3(M_ / 64, E_ / 64), 256>>>(Wo, bo, out);
}

// round 2
// speedup vs baseline: 1.0014x; 1.0014x over previous
#include <cuda_runtime.h>

#define B_ 8
#define S_ 1024
#define E_ 768
#define H_ 12
#define D_ 64
#define M_ (B_*S_)   // 8192

// Scratch (allocations are forbidden; use device globals)
__device__ float g_q[B_*H_*S_*D_];
__device__ float g_k[B_*H_*S_*D_];
__device__ float g_v[B_*H_*S_*D_];
__device__ float g_x[B_*S_*E_];   // attention output, already head-concatenated [B,S,E]

// ---------------------------------------------------------------------------
// Kernel 1: fused QKV projection.
// C[m, (h,d)] = sum_e hid[m,e] * W[h,e,d] + bias[h,d]
// grid = (M/64, 3*H). blockIdx.y selects (proj, head). 64x64 tile, K-tile 16,
// 256 threads, 4x4 microtile. Output scattered to [B,H,S,D] for attention.
// ---------------------------------------------------------------------------
__global__ __launch_bounds__(256)
void qkv_kernel(const float* __restrict__ hid,
                const float* __restrict__ Wq, const float* __restrict__ Wk,
                const float* __restrict__ Wv,
                const float* __restrict__ bq, const float* __restrict__ bk,
                const float* __restrict__ bv)
{
    __shared__ float AsT[16][64];   // [k][m]
    __shared__ float Bs [16][64];   // [k][n]

    const int tid = threadIdx.x;
    const int tx = tid & 15, ty = tid >> 4;
    const int m0 = blockIdx.x * 64;
    const int nb = blockIdx.y;
    const int proj = nb / H_;            // 0:q 1:k 2:v
    const int h = nb - proj * H_;

    const float* W    = (proj == 0) ? Wq : (proj == 1) ? Wk : Wv;
    const float* bias = (proj == 0) ? bq : (proj == 1) ? bk : bv;
    float* out        = (proj == 0) ? g_q : (proj == 1) ? g_k : g_v;
    const float* Wh = W + (size_t)h * E_ * D_;

    float acc[4][4] = {};

    const int a_row = tid >> 2;          // 0..63
    const int a_k   = (tid & 3) * 4;     // 0,4,8,12
    const int b_k   = tid >> 4;          // 0..15
    const int b_d   = (tid & 15) * 4;    // 0..60

    for (int k0 = 0; k0 < E_; k0 += 16) {
        float4 av = *(const float4*)&hid[(size_t)(m0 + a_row) * E_ + k0 + a_k];
        AsT[a_k + 0][a_row] = av.x;
        AsT[a_k + 1][a_row] = av.y;
        AsT[a_k + 2][a_row] = av.z;
        AsT[a_k + 3][a_row] = av.w;
        *(float4*)&Bs[b_k][b_d] =
            *(const float4*)&Wh[(size_t)(k0 + b_k) * D_ + b_d];
        __syncthreads();
#pragma unroll
        for (int kk = 0; kk < 16; kk++) {
            float4 a4 = *(const float4*)&AsT[kk][ty * 4];
            float4 b4 = *(const float4*)&Bs[kk][tx * 4];
            float a[4] = {a4.x, a4.y, a4.z, a4.w};
            float b[4] = {b4.x, b4.y, b4.z, b4.w};
#pragma unroll
            for (int i = 0; i < 4; i++)
#pragma unroll
                for (int j = 0; j < 4; j++)
                    acc[i][j] += a[i] * b[j];
        }
        __syncthreads();
    }

    float4 bb = *(const float4*)&bias[h * D_ + tx * 4];
#pragma unroll
    for (int i = 0; i < 4; i++) {
        int m = m0 + ty * 4 + i;
        int b = m >> 10;         // / S_
        int s = m & (S_ - 1);
        float* orow = out + (((size_t)(b * H_ + h)) * S_ + s) * D_;
        float4 ov = make_float4(acc[i][0] + bb.x, acc[i][1] + bb.y,
                                acc[i][2] + bb.z, acc[i][3] + bb.w);
        *(float4*)&orow[tx * 4] = ov;
    }
}

// ---------------------------------------------------------------------------
// Kernel 2: flash attention (fp32, non-causal).
// grid = (S/64, B*H), 256 threads. Each block: 64 Q rows, loop over 16 KV
// tiles of 64 rows. Smem operands are k-major for conflict-free LDS.128.
// Output written head-concatenated into g_x [B,S,E].
// ---------------------------------------------------------------------------
__global__ __launch_bounds__(256)
void attn_kernel()
{
    extern __shared__ float sm[];
    float* QsT = sm;               // [d][qrow]   64*64
    float* KsT = sm + 4096;        // [d][kvrow]  64*64
    float* Vs  = sm + 8192;        // [kvrow][d]  64*64
    float* Ps  = sm + 12288;       // [kvrow][qrow] 64*65 (pad for stores)

    const int tid = threadIdx.x;
    const int tx = tid & 15, ty = tid >> 4;
    const int bh = blockIdx.y;          // b*H + h
    const int s0 = blockIdx.x * 64;
    const int b = bh / H_;
    const int h = bh - b * H_;

    const float* Q = g_q + (size_t)bh * S_ * D_;
    const float* K = g_k + (size_t)bh * S_ * D_;
    const float* V = g_v + (size_t)bh * S_ * D_;

    // load Q tile, transposed to [d][qrow]
#pragma unroll
    for (int p = 0; p < 4; p++) {
        int fid = p * 256 + tid;
        int row = fid >> 4;
        int dq  = (fid & 15) * 4;
        float4 qv = *(const float4*)&Q[(size_t)(s0 + row) * D_ + dq];
        QsT[(dq + 0) * 64 + row] = qv.x;
        QsT[(dq + 1) * 64 + row] = qv.y;
        QsT[(dq + 2) * 64 + row] = qv.z;
        QsT[(dq + 3) * 64 + row] = qv.w;
    }

    float m_i[4], l_i[4], o[4][4];
#pragma unroll
    for (int i = 0; i < 4; i++) {
        m_i[i] = -1e30f; l_i[i] = 0.f;
#pragma unroll
        for (int j = 0; j < 4; j++) o[i][j] = 0.f;
    }

    for (int t0 = 0; t0 < S_; t0 += 64) {
        // load K (transposed) and V tiles
#pragma unroll
        for (int p = 0; p < 4; p++) {
            int fid = p * 256 + tid;
            int row = fid >> 4;
            int dq  = (fid & 15) * 4;
            float4 kv4 = *(const float4*)&K[(size_t)(t0 + row) * D_ + dq];
            KsT[(dq + 0) * 64 + row] = kv4.x;
            KsT[(dq + 1) * 64 + row] = kv4.y;
            KsT[(dq + 2) * 64 + row] = kv4.z;
            KsT[(dq + 3) * 64 + row] = kv4.w;
            *(float4*)&Vs[row * 64 + dq] =
                *(const float4*)&V[(size_t)(t0 + row) * D_ + dq];
        }
        __syncthreads();

        // S = Q K^T (per-thread 4x4)
        float sc[4][4] = {};
#pragma unroll
        for (int kd = 0; kd < 64; kd++) {
            float4 a4 = *(const float4*)&QsT[kd * 64 + ty * 4];
            float4 b4 = *(const float4*)&KsT[kd * 64 + tx * 4];
            float a[4] = {a4.x, a4.y, a4.z, a4.w};
            float bb[4] = {b4.x, b4.y, b4.z, b4.w};
#pragma unroll
            for (int i = 0; i < 4; i++)
#pragma unroll
                for (int j = 0; j < 4; j++)
                    sc[i][j] += a[i] * bb[j];
        }

        // online softmax (rows owned by (ty,i), 16 tx lanes share a row)
#pragma unroll
        for (int i = 0; i < 4; i++) {
            float mx = -1e30f;
#pragma unroll
            for (int j = 0; j < 4; j++) {
                sc[i][j] *= 0.125f;          // 1/sqrt(64)
                mx = fmaxf(mx, sc[i][j]);
            }
#pragma unroll
            for (int off = 8; off > 0; off >>= 1)
                mx = fmaxf(mx, __shfl_xor_sync(0xffffffffu, mx, off));
            float mnew = fmaxf(m_i[i], mx);
            float corr = __expf(m_i[i] - mnew);
            float rs = 0.f;
#pragma unroll
            for (int j = 0; j < 4; j++) {
                float p = __expf(sc[i][j] - mnew);
                Ps[(tx * 4 + j) * 65 + ty * 4 + i] = p;
                rs += p;
            }
#pragma unroll
            for (int off = 8; off > 0; off >>= 1)
                rs += __shfl_xor_sync(0xffffffffu, rs, off);
            l_i[i] = l_i[i] * corr + rs;
            m_i[i] = mnew;
#pragma unroll
            for (int j = 0; j < 4; j++) o[i][j] *= corr;
        }
        __syncthreads();

        // O += P @ V
#pragma unroll
        for (int kd = 0; kd < 64; kd++) {
            float pr[4];
#pragma unroll
            for (int i = 0; i < 4; i++)
                pr[i] = Ps[kd * 65 + ty * 4 + i];
            float4 v4 = *(const float4*)&Vs[kd * 64 + tx * 4];
            float vv[4] = {v4.x, v4.y, v4.z, v4.w};
#pragma unroll
            for (int i = 0; i < 4; i++)
#pragma unroll
                for (int j = 0; j < 4; j++)
                    o[i][j] += pr[i] * vv[j];
        }
        __syncthreads();
    }

    // finalize + write head-concatenated
#pragma unroll
    for (int i = 0; i < 4; i++) {
        float inv = 1.f / l_i[i];
        int qr = s0 + ty * 4 + i;
        float* row = g_x + ((size_t)b * S_ + qr) * E_ + h * D_;
        float4 ov = make_float4(o[i][0] * inv, o[i][1] * inv,
                                o[i][2] * inv, o[i][3] * inv);
        *(float4*)&row[tx * 4] = ov;
    }
}

// ---------------------------------------------------------------------------
// Kernel 3: output projection.  out = g_x @ Wo + bo.  grid = (M/64, E/64).
// ---------------------------------------------------------------------------
__global__ __launch_bounds__(256)
void proj_kernel(const float* __restrict__ Wo, const float* __restrict__ bo,
                 float* __restrict__ out)
{
    __shared__ float AsT[16][64];
    __shared__ float Bs [16][64];

    const int tid = threadIdx.x;
    const int tx = tid & 15, ty = tid >> 4;
    const int m0 = blockIdx.x * 64;
    const int n0 = blockIdx.y * 64;

    float acc[4][4] = {};

    const int a_row = tid >> 2;
    const int a_k   = (tid & 3) * 4;
    const int b_k   = tid >> 4;
    const int b_d   = (tid & 15) * 4;

    for (int k0 = 0; k0 < E_; k0 += 16) {
        float4 av = *(const float4*)&g_x[(size_t)(m0 + a_row) * E_ + k0 + a_k];
        AsT[a_k + 0][a_row] = av.x;
        AsT[a_k + 1][a_row] = av.y;
        AsT[a_k + 2][a_row] = av.z;
        AsT[a_k + 3][a_row] = av.w;
        *(float4*)&Bs[b_k][b_d] =
            *(const float4*)&Wo[(size_t)(k0 + b_k) * E_ + n0 + b_d];
        __syncthreads();
#pragma unroll
        for (int kk = 0; kk < 16; kk++) {
            float4 a4 = *(const float4*)&AsT[kk][ty * 4];
            float4 b4 = *(const float4*)&Bs[kk][tx * 4];
            float a[4] = {a4.x, a4.y, a4.z, a4.w};
            float b[4] = {b4.x, b4.y, b4.z, b4.w};
#pragma unroll
            for (int i = 0; i < 4; i++)
#pragma unroll
                for (int j = 0; j < 4; j++)
                    acc[i][j] += a[i] * b[j];
        }
        __syncthreads();
    }

    float4 bb = *(const float4*)&bo[n0 + tx * 4];
#pragma unroll
    for (int i = 0; i < 4; i++) {
        int m = m0 + ty * 4 + i;
        float4 ov = make_float4(acc[i][0] + bb.x, acc[i][1] + bb.y,
                                acc[i][2] + bb.z, acc[i][3] + bb.w);
        *(float4*)&out[(size_t)m * E_ + n0 + tx * 4] = ov;
    }
}

// ---------------------------------------------------------------------------

extern "C" void kernel_launch(void* const* d_in, const int* in_sizes, int n_in,
                              void* d_out, int out_size)
{
    const float* hid = (const float*)d_in[0];
    const float* Wq  = (const float*)d_in[1];
    const float* Wk  = (const float*)d_in[2];
    const float* Wv  = (const float*)d_in[3];
    const float* bq  = (const float*)d_in[4];
    const float* bk  = (const float*)d_in[5];
    const float* bv  = (const float*)d_in[6];
    const float* Wo  = (const float*)d_in[7];
    const float* bo  = (const float*)d_in[8];
    float* out = (float*)d_out;

    const int attn_smem = (3 * 64 * 64 + 64 * 65) * (int)sizeof(float); // 65792
    cudaFuncSetAttribute(attn_kernel,
                         cudaFuncAttributeMaxDynamicSharedMemorySize, attn_smem);

    qkv_kernel<<<dim3(M_ / 64, 3 * H_), 256>>>(hid, Wq, Wk, Wv, bq, bk, bv);
    attn_kernel<<<dim3(S_ / 64, B_ * H_), 256, attn_smem>>>();
    proj_kernel<<<dim3(M_ / 64, E_ / 64), 256>>>(Wo, bo, out);
}

// round 3
// speedup vs baseline: 1.0015x; 1.0001x over previous
#include <cuda_runtime.h>

#define B_ 8
#define S_ 1024
#define E_ 768
#define H_ 12
#define D_ 64
#define M_ (B_*S_)   // 8192

// Scratch (allocations are forbidden; use device globals)
__device__ float g_q[B_*H_*S_*D_];
__device__ float g_k[B_*H_*S_*D_];
__device__ float g_v[B_*H_*S_*D_];
__device__ float g_x[B_*S_*E_];   // attention output, already head-concatenated [B,S,E]

// ---------------------------------------------------------------------------
// Kernel 1: fused QKV projection.
// C[m, (h,d)] = sum_e hid[m,e] * W[h,e,d] + bias[h,d]
// grid = (M/64, 3*H). blockIdx.y selects (proj, head). 64x64 tile, K-tile 16,
// 256 threads, 4x4 microtile. Output scattered to [B,H,S,D] for attention.
// ---------------------------------------------------------------------------
__global__ __launch_bounds__(256)
void qkv_kernel(const float* __restrict__ hid,
                const float* __restrict__ Wq, const float* __restrict__ Wk,
                const float* __restrict__ Wv,
                const float* __restrict__ bq, const float* __restrict__ bk,
                const float* __restrict__ bv)
{
    __shared__ float AsT[16][64];   // [k][m]
    __shared__ float Bs [16][64];   // [k][n]

    const int tid = threadIdx.x;
    const int tx = tid & 15, ty = tid >> 4;
    const int m0 = blockIdx.x * 64;
    const int nb = blockIdx.y;
    const int proj = nb / H_;            // 0:q 1:k 2:v
    const int h = nb - proj * H_;

    const float* W    = (proj == 0) ? Wq : (proj == 1) ? Wk : Wv;
    const float* bias = (proj == 0) ? bq : (proj == 1) ? bk : bv;
    float* out        = (proj == 0) ? g_q : (proj == 1) ? g_k : g_v;
    const float* Wh = W + (size_t)h * E_ * D_;

    float acc[4][4] = {};

    const int a_row = tid >> 2;          // 0..63
    const int a_k   = (tid & 3) * 4;     // 0,4,8,12
    const int b_k   = tid >> 4;          // 0..15
    const int b_d   = (tid & 15) * 4;    // 0..60

    for (int k0 = 0; k0 < E_; k0 += 16) {
        float4 av = *(const float4*)&hid[(size_t)(m0 + a_row) * E_ + k0 + a_k];
        AsT[a_k + 0][a_row] = av.x;
        AsT[a_k + 1][a_row] = av.y;
        AsT[a_k + 2][a_row] = av.z;
        AsT[a_k + 3][a_row] = av.w;
        *(float4*)&Bs[b_k][b_d] =
            *(const float4*)&Wh[(size_t)(k0 + b_k) * D_ + b_d];
        __syncthreads();
#pragma unroll
        for (int kk = 0; kk < 16; kk++) {
            float4 a4 = *(const float4*)&AsT[kk][ty * 4];
            float4 b4 = *(const float4*)&Bs[kk][tx * 4];
            float a[4] = {a4.x, a4.y, a4.z, a4.w};
            float b[4] = {b4.x, b4.y, b4.z, b4.w};
#pragma unroll
            for (int i = 0; i < 4; i++)
#pragma unroll
                for (int j = 0; j < 4; j++)
                    acc[i][j] += a[i] * b[j];
        }
        __syncthreads();
    }

    float4 bb = *(const float4*)&bias[h * D_ + tx * 4];
#pragma unroll
    for (int i = 0; i < 4; i++) {
        int m = m0 + ty * 4 + i;
        int b = m >> 10;         // / S_
        int s = m & (S_ - 1);
        float* orow = out + (((size_t)(b * H_ + h)) * S_ + s) * D_;
        float4 ov = make_float4(acc[i][0] + bb.x, acc[i][1] + bb.y,
                                acc[i][2] + bb.z, acc[i][3] + bb.w);
        *(float4*)&orow[tx * 4] = ov;
    }
}

// ---------------------------------------------------------------------------
// Kernel 2: flash attention (fp32, non-causal).
// grid = (S/64, B*H), 256 threads. Each block: 64 Q rows, loop over 16 KV
// tiles of 64 rows. Smem operands are k-major for conflict-free LDS.128.
// Output written head-concatenated into g_x [B,S,E].
// ---------------------------------------------------------------------------
__global__ __launch_bounds__(256)
void attn_kernel()
{
    extern __shared__ float sm[];
    float* QsT = sm;               // [d][qrow]   64*64
    float* KsT = sm + 4096;        // [d][kvrow]  64*64
    float* Vs  = sm + 8192;        // [kvrow][d]  64*64
    float* Ps  = sm + 12288;       // [kvrow][qrow] 64*65 (pad for stores)

    const int tid = threadIdx.x;
    const int tx = tid & 15, ty = tid >> 4;
    const int bh = blockIdx.y;          // b*H + h
    const int s0 = blockIdx.x * 64;
    const int b = bh / H_;
    const int h = bh - b * H_;

    const float* Q = g_q + (size_t)bh * S_ * D_;
    const float* K = g_k + (size_t)bh * S_ * D_;
    const float* V = g_v + (size_t)bh * S_ * D_;

    // load Q tile, transposed to [d][qrow]
#pragma unroll
    for (int p = 0; p < 4; p++) {
        int fid = p * 256 + tid;
        int row = fid >> 4;
        int dq  = (fid & 15) * 4;
        float4 qv = *(const float4*)&Q[(size_t)(s0 + row) * D_ + dq];
        QsT[(dq + 0) * 64 + row] = qv.x;
        QsT[(dq + 1) * 64 + row] = qv.y;
        QsT[(dq + 2) * 64 + row] = qv.z;
        QsT[(dq + 3) * 64 + row] = qv.w;
    }

    float m_i[4], l_i[4], o[4][4];
#pragma unroll
    for (int i = 0; i < 4; i++) {
        m_i[i] = -1e30f; l_i[i] = 0.f;
#pragma unroll
        for (int j = 0; j < 4; j++) o[i][j] = 0.f;
    }

    for (int t0 = 0; t0 < S_; t0 += 64) {
        // load K (transposed) and V tiles
#pragma unroll
        for (int p = 0; p < 4; p++) {
            int fid = p * 256 + tid;
            int row = fid >> 4;
            int dq  = (fid & 15) * 4;
            float4 kv4 = *(const float4*)&K[(size_t)(t0 + row) * D_ + dq];
            KsT[(dq + 0) * 64 + row] = kv4.x;
            KsT[(dq + 1) * 64 + row] = kv4.y;
            KsT[(dq + 2) * 64 + row] = kv4.z;
            KsT[(dq + 3) * 64 + row] = kv4.w;
            *(float4*)&Vs[row * 64 + dq] =
                *(const float4*)&V[(size_t)(t0 + row) * D_ + dq];
        }
        __syncthreads();

        // S = Q K^T (per-thread 4x4)
        float sc[4][4] = {};
#pragma unroll
        for (int kd = 0; kd < 64; kd++) {
            float4 a4 = *(const float4*)&QsT[kd * 64 + ty * 4];
            float4 b4 = *(const float4*)&KsT[kd * 64 + tx * 4];
            float a[4] = {a4.x, a4.y, a4.z, a4.w};
            float bb[4] = {b4.x, b4.y, b4.z, b4.w};
#pragma unroll
            for (int i = 0; i < 4; i++)
#pragma unroll
                for (int j = 0; j < 4; j++)
                    sc[i][j] += a[i] * bb[j];
        }

        // online softmax (rows owned by (ty,i), 16 tx lanes share a row)
#pragma unroll
        for (int i = 0; i < 4; i++) {
            float mx = -1e30f;
#pragma unroll
            for (int j = 0; j < 4; j++) {
                sc[i][j] *= 0.125f;          // 1/sqrt(64)
                mx = fmaxf(mx, sc[i][j]);
            }
#pragma unroll
            for (int off = 8; off > 0; off >>= 1)
                mx = fmaxf(mx, __shfl_xor_sync(0xffffffffu, mx, off));
            float mnew = fmaxf(m_i[i], mx);
            float corr = __expf(m_i[i] - mnew);
            float rs = 0.f;
#pragma unroll
            for (int j = 0; j < 4; j++) {
                float p = __expf(sc[i][j] - mnew);
                Ps[(tx * 4 + j) * 65 + ty * 4 + i] = p;
                rs += p;
            }
#pragma unroll
            for (int off = 8; off > 0; off >>= 1)
                rs += __shfl_xor_sync(0xffffffffu, rs, off);
            l_i[i] = l_i[i] * corr + rs;
            m_i[i] = mnew;
#pragma unroll
            for (int j = 0; j < 4; j++) o[i][j] *= corr;
        }
        __syncthreads();

        // O += P @ V
#pragma unroll
        for (int kd = 0; kd < 64; kd++) {
            float pr[4];
#pragma unroll
            for (int i = 0; i < 4; i++)
                pr[i] = Ps[kd * 65 + ty * 4 + i];
            float4 v4 = *(const float4*)&Vs[kd * 64 + tx * 4];
            float vv[4] = {v4.x, v4.y, v4.z, v4.w};
#pragma unroll
            for (int i = 0; i < 4; i++)
#pragma unroll
                for (int j = 0; j < 4; j++)
                    o[i][j] += pr[i] * vv[j];
        }
        __syncthreads();
    }

    // finalize + write head-concatenated
#pragma unroll
    for (int i = 0; i < 4; i++) {
        float inv = 1.f / l_i[i];
        int qr = s0 + ty * 4 + i;
        float* row = g_x + ((size_t)b * S_ + qr) * E_ + h * D_;
        float4 ov = make_float4(o[i][0] * inv, o[i][1] * inv,
                                o[i][2] * inv, o[i][3] * inv);
        *(float4*)&row[tx * 4] = ov;
    }
}

// ---------------------------------------------------------------------------
// Kernel 3: output projection.  out = g_x @ Wo + bo.  grid = (M/64, E/64).
// ---------------------------------------------------------------------------
__global__ __launch_bounds__(256)
void proj_kernel(const float* __restrict__ Wo, const float* __restrict__ bo,
                 float* __restrict__ out)
{
    __shared__ float AsT[16][64];
    __shared__ float Bs [16][64];

    const int tid = threadIdx.x;
    const int tx = tid & 15, ty = tid >> 4;
    const int m0 = blockIdx.x * 64;
    const int n0 = blockIdx.y * 64;

    float acc[4][4] = {};

    const int a_row = tid >> 2;
    const int a_k   = (tid & 3) * 4;
    const int b_k   = tid >> 4;
    const int b_d   = (tid & 15) * 4;

    for (int k0 = 0; k0 < E_; k0 += 16) {
        float4 av = *(const float4*)&g_x[(size_t)(m0 + a_row) * E_ + k0 + a_k];
        AsT[a_k + 0][a_row] = av.x;
        AsT[a_k + 1][a_row] = av.y;
        AsT[a_k + 2][a_row] = av.z;
        AsT[a_k + 3][a_row] = av.w;
        *(float4*)&Bs[b_k][b_d] =
            *(const float4*)&Wo[(size_t)(k0 + b_k) * E_ + n0 + b_d];
        __syncthreads();
#pragma unroll
        for (int kk = 0; kk < 16; kk++) {
            float4 a4 = *(const float4*)&AsT[kk][ty * 4];
            float4 b4 = *(const float4*)&Bs[kk][tx * 4];
            float a[4] = {a4.x, a4.y, a4.z, a4.w};
            float b[4] = {b4.x, b4.y, b4.z, b4.w};
#pragma unroll
            for (int i = 0; i < 4; i++)
#pragma unroll
                for (int j = 0; j < 4; j++)
                    acc[i][j] += a[i] * b[j];
        }
        __syncthreads();
    }

    float4 bb = *(const float4*)&bo[n0 + tx * 4];
#pragma unroll
    for (int i = 0; i < 4; i++) {
        int m = m0 + ty * 4 + i;
        float4 ov = make_float4(acc[i][0] + bb.x, acc[i][1] + bb.y,
                                acc[i][2] + bb.z, acc[i][3] + bb.w);
        *(float4*)&out[(size_t)m * E_ + n0 + tx * 4] = ov;
    }
}

// ---------------------------------------------------------------------------

extern "C" void kernel_launch(void* const* d_in, const int* in_sizes, int n_in,
                              void* d_out, int out_size)
{
    const float* hid = (const float*)d_in[0];
    const float* Wq  = (const float*)d_in[1];
    const float* Wk  = (const float*)d_in[2];
    const float* Wv  = (const float*)d_in[3];
    const float* bq  = (const float*)d_in[4];
    const float* bk  = (const float*)d_in[5];
    const float* bv  = (const float*)d_in[6];
    const float* Wo  = (const float*)d_in[7];
    const float* bo  = (const float*)d_in[8];
    float* out = (float*)d_out;

    const int attn_smem = (3 * 64 * 64 + 64 * 65) * (int)sizeof(float); // 65792
    cudaFuncSetAttribute(attn_kernel,
                         cudaFuncAttributeMaxDynamicSharedMemorySize, attn_smem);

    qkv_kernel<<<dim3(M_ / 64, 3 * H_), 256>>>(hid, Wq, Wk, Wv, bq, bk, bv);
    attn_kernel<<<dim3(S_ / 64, B_ * H_), 256, attn_smem>>>();
    proj_kernel<<<dim3(M_ / 64, E_ / 64), 256>>>(Wo, bo, out);
}